// round 2
// baseline (speedup 1.0000x reference)
#include <cuda_runtime.h>

#define NP 8192
#define THREADS 256
#define IPT 4
#define IB (NP / (THREADS * IPT))   // 8 i-blocks
#define JC 37
#define JCHUNK 222                  // 37*222 = 8214 >= 8192

static_assert(IB * THREADS * IPT == NP, "i coverage");
static_assert(JC * JCHUNK >= NP, "j coverage");

// Deterministic scratch: every (chunk, i) slot is written exactly once per launch.
__device__ float g_psum[JC * NP];
__device__ int   g_pcnt[JC * NP];

__global__ __launch_bounds__(THREADS)
void pair_kernel(const float2* __restrict__ past, const float2* __restrict__ pos) {
    __shared__ float2 sj[JCHUNK];
    const int ib   = blockIdx.x;
    const int jc   = blockIdx.y;
    const int tid  = threadIdx.x;
    const int jbase = jc * JCHUNK;
    const int jend  = min(NP - jbase, JCHUNK);

    for (int t = tid; t < jend; t += THREADS) sj[t] = pos[jbase + t];
    __syncthreads();

    const int i0 = ib * (THREADS * IPT);

    float c[IPT], ns[IPT], s[IPT], a[IPT], b[IPT], sum[IPT];
    int   ii[IPT], cnt[IPT];

    #pragma unroll
    for (int k = 0; k < IPT; k++) {
        const int i = i0 + k * THREADS + tid;
        ii[k] = i;
        const float2 p = pos[i];
        const float2 q = past[i];
        const float dx = p.x - q.x;
        const float dy = p.y - q.y;
        const float l2 = fmaf(dx, dx, dy * dy);
        float ci, si;
        if (l2 > 0.0f) {
            float rin;
            asm("rsqrt.approx.f32 %0, %1;" : "=f"(rin) : "f"(l2));
            ci = dx * rin;
            si = dy * rin;
        } else {             // zero displacement -> atan2(0,0) = 0 -> heading 0
            ci = 1.0f;
            si = 0.0f;
        }
        c[k]  = ci;
        s[k]  = si;
        ns[k] = -si;
        a[k]  = -fmaf(p.x, ci, p.y * si);    // -(x_i*c + y_i*s)
        b[k]  =  fmaf(p.x, si, -(p.y * ci)); // x_i*s - y_i*c
        sum[k] = 0.0f;
        cnt[k] = 0;
    }

    const float T35 = 0.70020753f;  // tan(35 deg)

    for (int jj = 0; jj < jend; jj++) {
        const float2 pj = sj[jj];
        const int jg = jbase + jj;
        #pragma unroll
        for (int k = 0; k < IPT; k++) {
            // rotate rel = pos[j]-pos[i] by -heading_i
            const float xp = fmaf(pj.x, c[k],  fmaf(pj.y, s[k],  a[k]));
            const float yp = fmaf(pj.y, c[k],  fmaf(pj.x, ns[k], b[k]));
            const float sq = fmaf(xp, xp, yp * yp);
            float d;
            asm("sqrt.approx.f32 %0, %1;" : "=f"(d) : "f"(sq));
            const float t = xp * T35;
            // in-arc: x'>0 and |y'| < x'*tan(35)  (x'>0 implied); exclude self
            const bool vis = (fabsf(yp) < t) && (jg != ii[k]);
            if (vis) { sum[k] += d; cnt[k]++; }
        }
    }

    #pragma unroll
    for (int k = 0; k < IPT; k++) {
        g_psum[jc * NP + ii[k]] = sum[k];
        g_pcnt[jc * NP + ii[k]] = cnt[k];
    }
}

__global__ void finalize_kernel(const int* __restrict__ idxmask,
                                const float* __restrict__ radii,
                                float* __restrict__ out) {
    const int i = blockIdx.x * blockDim.x + threadIdx.x;
    if (i >= NP) return;
    float s = 0.0f;
    int   c = 0;
    #pragma unroll
    for (int jc = 0; jc < JC; jc++) {
        s += g_psum[jc * NP + i];
        c += g_pcnt[jc * NP + i];
    }
    float mean = (c > 0) ? (s / (float)c) : 0.0f;
    mean = fminf(fmaxf(mean, 0.2f), 5.0f);            // clip [MIN_D, MAX_D]
    const float reg = (mean - 0.2f) * (1.0f / 4.8f);  // (d-MIN_D)/(MAX_D-MIN_D)
    const float r   = fmaf(reg, 3.5f, 0.5f);          // MIN_R + reg*(MAX_R-MIN_R)
    out[i] = idxmask[i] ? r : radii[i];
}

extern "C" void kernel_launch(void* const* d_in, const int* in_sizes, int n_in,
                              void* d_out, int out_size) {
    const float2* past = (const float2*)d_in[0];        // past_ped_positions [N,2] f32
    const float2* pos  = (const float2*)d_in[1];        // ped_positions      [N,2] f32
    const int* idxm    = (const int*)d_in[2];           // indexes [N] (bool widened to int32)
    const float* radii = (const float*)d_in[3];         // all_radii [N] f32
    float* out = (float*)d_out;

    dim3 grid(IB, JC);
    pair_kernel<<<grid, THREADS>>>(past, pos);
    finalize_kernel<<<NP / 256, 256>>>(idxm, radii, out);
}